// round 14
// baseline (speedup 1.0000x reference)
#include <cuda_runtime.h>

#define NB 2
#define NH 16
#define NT 8192
#define ND 64
#define NM 8
#define NP 32                       // ND/2
#define BHTD (NB*NH*NT*ND)          // 33554432
#define TB 32                       // tokens per block
#define VEC 64                      // vectors per block (32 q + 32 k)
#define THREADS 256
#define CS_BLOCKS 1024              // 1024*256 = NT*NP threads

typedef unsigned long long u64;

// Scratch (allocation-free): normalized Householder vectors + cos/sin table
__device__ float  g_U[NH*NM*ND];    // 8192 floats
__device__ float2 g_cs[NT*NP];      // 2 MB

// ---------------- packed f32x2 helpers ----------------
__device__ __forceinline__ u64 pack2(float lo, float hi) {
    u64 r; asm("mov.b64 %0, {%1,%2};" : "=l"(r) : "f"(lo), "f"(hi)); return r;
}
__device__ __forceinline__ void unpack2(u64 a, float& lo, float& hi) {
    asm("mov.b64 {%0,%1}, %2;" : "=f"(lo), "=f"(hi) : "l"(a));
}
__device__ __forceinline__ u64 ffma2(u64 a, u64 b, u64 c) {
    u64 d; asm("fma.rn.f32x2 %0, %1, %2, %3;" : "=l"(d) : "l"(a), "l"(b), "l"(c));
    return d;
}

// ---------------- fused prep kernel ----------------
__global__ void prep(const float* __restrict__ V, const float* __restrict__ pos,
                     const float* __restrict__ freq)
{
    int b = blockIdx.x;
    if (b < CS_BLOCKS) {
        int idx = b*256 + threadIdx.x;       // 0 .. NT*NP-1
        int t = idx >> 5, p = idx & 31;
        float a = pos[t] * freq[p];
        float s, c;
        sincosf(a, &s, &c);
        g_cs[idx] = make_float2(c, s);
    } else {
        int rb = b - CS_BLOCKS;              // 0..15
        int w = threadIdx.x >> 5, l = threadIdx.x & 31;
        int row = rb*8 + w;                  // 0..127 (= NH*NM-1)
        float a  = V[row*ND + l];
        float bb = V[row*ND + 32 + l];
        float s = a*a + bb*bb;
        #pragma unroll
        for (int o = 16; o; o >>= 1) s += __shfl_xor_sync(0xffffffffu, s, o);
        float inv = rsqrtf(s + 1e-16f);      // EPS^2
        g_U[row*ND + l]      = a*inv;
        g_U[row*ND + 32 + l] = bb*inv;
    }
}

// ---------------- main kernel ----------------
// Block: 256 threads = 32 tokens x {q,k} = 64 vectors. Thread = (vector v = tid>>2,
// segment s = tid&3) owns 16 consecutive floats (8 packed f32x2 pairs).
// Dot products close over the 4-lane group with 2 shfl_xor.
// Padded smem layout (float4 units): vector row pitch 20, segment stride 5
//  -> word addresses v*80 + s*20 + j*4: the 8 accesses of a phase partition all
//     32 banks exactly (conflict-free LDS.128/STS.128 on the owner path).

__global__ __launch_bounds__(THREADS) void hh_rope(
    const float* __restrict__ q, const float* __restrict__ k, float* __restrict__ out)
{
    __shared__ float4 zbuf[VEC*20];     // 20480 B
    __shared__ float4 ubuf[NM*20];      //  2560 B

    const int tid = threadIdx.x;
    const int bx  = blockIdx.x;         // token tile (NT/TB = 256)
    const int by  = blockIdx.y;         // b*NH + h   (32)
    const int h   = by & (NH-1);
    const int t0  = bx * TB;

    // Stage U for this head: 128 float4, padded layout
    if (tid < 128) {
        const float4* gu = (const float4*)g_U + (size_t)h*128;
        float4 val = gu[tid];
        int m = tid >> 4, jj = tid & 15;
        ubuf[m*20 + (jj>>2)*5 + (jj&3)] = val;
    }
    // Stage q (vectors 0..31) and k (32..63), coalesced LDG.128
    const size_t base = ((size_t)by*NT + t0) * (ND/4);   // float4 index
    const float4* qb = (const float4*)q + base;
    const float4* kb = (const float4*)k + base;
    #pragma unroll
    for (int i = 0; i < 2; i++) {
        int f = i*THREADS + tid;        // 0..511
        int v = f >> 4, jj = f & 15;
        zbuf[v*20 + (jj>>2)*5 + (jj&3)] = qb[f];
    }
    #pragma unroll
    for (int i = 0; i < 2; i++) {
        int f = i*THREADS + tid;
        int v = f >> 4, jj = f & 15;
        zbuf[(v+32)*20 + (jj>>2)*5 + (jj&3)] = kb[f];
    }
    __syncthreads();

    const int v = tid >> 2;             // 0..63
    const int s = tid & 3;              // segment

    // Own 16 floats -> 8 packed pairs
    u64 zz[8];
    {
        const ulonglong2* zr = (const ulonglong2*)(zbuf + v*20 + s*5);
        #pragma unroll
        for (int j = 0; j < 4; j++) { ulonglong2 t = zr[j]; zz[2*j] = t.x; zz[2*j+1] = t.y; }
    }

    // 8 Householder reflections, m = 7..0 (matches reference order).
    // u segment kept in registers across dot + update (single smem read).
    #pragma unroll 1
    for (int m = NM - 1; m >= 0; m--) {
        const ulonglong2* ur = (const ulonglong2*)(ubuf + m*20 + s*5);
        u64 uu[8];
        #pragma unroll
        for (int j = 0; j < 4; j++) { ulonglong2 t = ur[j]; uu[2*j] = t.x; uu[2*j+1] = t.y; }
        u64 acc0 = 0ull, acc1 = 0ull;
        #pragma unroll
        for (int j = 0; j < 4; j++) {
            acc0 = ffma2(zz[2*j],   uu[2*j],   acc0);
            acc1 = ffma2(zz[2*j+1], uu[2*j+1], acc1);
        }
        float a0, a1, a2, a3;
        unpack2(acc0, a0, a1);
        unpack2(acc1, a2, a3);
        float ssum = (a0 + a1) + (a2 + a3);
        ssum += __shfl_xor_sync(0xffffffffu, ssum, 1);
        ssum += __shfl_xor_sync(0xffffffffu, ssum, 2);
        float c = -2.0f * ssum;
        u64 cc = pack2(c, c);
        #pragma unroll
        for (int j = 0; j < 8; j++) zz[j] = ffma2(cc, uu[j], zz[j]);
    }

    // RoPE: pair p = s*8 + i; cs read straight from the L2-resident table
    {
        int tok = t0 + (v & 31);
        const float4* cs4 = (const float4*)(g_cs + (size_t)tok*NP + s*8);
        #pragma unroll
        for (int j = 0; j < 4; j++) {
            float4 cp = cs4[j];         // (c0, s0, c1, s1)
            float xe, xo;
            unpack2(zz[2*j], xe, xo);
            zz[2*j]   = pack2(fmaf(xe, cp.x, -(xo*cp.y)), fmaf(xe, cp.y, xo*cp.x));
            unpack2(zz[2*j+1], xe, xo);
            zz[2*j+1] = pack2(fmaf(xe, cp.z, -(xo*cp.w)), fmaf(xe, cp.w, xo*cp.z));
        }
    }

    // Write back own segment (no race: segments are exclusive), then coalesced store
    {
        ulonglong2* zr = (ulonglong2*)(zbuf + v*20 + s*5);
        #pragma unroll
        for (int j = 0; j < 4; j++) zr[j] = make_ulonglong2(zz[2*j], zz[2*j+1]);
    }
    __syncthreads();

    float4* oq = (float4*)out + base;
    float4* ok = (float4*)out + (size_t)(BHTD/4) + base;
    #pragma unroll
    for (int i = 0; i < 2; i++) {
        int f = i*THREADS + tid;
        int vv = f >> 4, jj = f & 15;
        oq[f] = zbuf[vv*20 + (jj>>2)*5 + (jj&3)];
    }
    #pragma unroll
    for (int i = 0; i < 2; i++) {
        int f = i*THREADS + tid;
        int vv = f >> 4, jj = f & 15;
        ok[f] = zbuf[(vv+32)*20 + (jj>>2)*5 + (jj&3)];
    }
}

// ---------------- launch ----------------

extern "C" void kernel_launch(void* const* d_in, const int* in_sizes, int n_in,
                              void* d_out, int out_size) {
    const float* q    = (const float*)d_in[0];
    const float* k    = (const float*)d_in[1];
    const float* V    = (const float*)d_in[2];
    const float* pos  = (const float*)d_in[3];
    const float* freq = (const float*)d_in[4];
    float* out = (float*)d_out;

    prep<<<CS_BLOCKS + 16, 256>>>(V, pos, freq);

    dim3 grid(NT/TB, NB*NH);
    hh_rope<<<grid, THREADS>>>(q, k, out);
}